// round 4
// baseline (speedup 1.0000x reference)
#include <cuda_runtime.h>
#include <cstdint>

#define BB 512
#define TT 1024
#define NN 64

// Two warps per batch element, 4 batches per 256-thread block, grid = 128
// (one block per SM, single wave). Pair p = warps (2p, 2p+1) -> lands on two
// DIFFERENT SMSPs; each warp owns 32 columns (one per thread), halving the
// per-step FMA2 issue (the R3 bottleneck) from 128 to 64 cycles.
//
// Linear-domain recurrence with integer-exponent renormalization:
//   q_j(t+1) = exp(x_j(t+1)) * (sum_i q_i(t) * E_ij) * 2^{-e_t}
// E = exp(trans) register-resident per column, packed over ROW pairs, so the
// p-vector loads are 16 x ld.shared.v2.u64 (broadcast) and each u64 feeds one
// fma.f32x2. p is exchanged via shared memory with a per-pair named barrier.
__global__ __launch_bounds__(256, 1) void crf_fwd_kernel(
    const float* __restrict__ inputs,   // [B, T, N] fp32
    const float* __restrict__ trans,    // [N, N] fp32
    const int*   __restrict__ tags,     // [B, T] int32
    const int*   __restrict__ lens,     // [B] int32
    float*       __restrict__ out)      // [B] fp32
{
    const int tid  = threadIdx.x;
    const int lane = tid & 31;
    const int wid  = tid >> 5;      // 0..7
    const int pair = wid >> 1;      // 0..3  (batch within block)
    const int role = wid & 1;       // 0 / 1 (column half)
    const int b    = blockIdx.x * 4 + pair;
    const int j    = role * 32 + lane;   // owned column
    const int L    = lens[b];
    const int barid = 1 + pair;

    __shared__ __align__(16) float pbuf[4][2][NN];
    __shared__ float ssum[4][2];

    // ---- E = exp(trans) column j, packed over row pairs ----
    unsigned long long E[NN / 2];
#pragma unroll
    for (int k = 0; k < NN / 2; ++k) {
        float e0 = __expf(trans[(2 * k)     * NN + j]);
        float e1 = __expf(trans[(2 * k + 1) * NN + j]);
        asm("mov.b64 %0, {%1,%2};" : "=l"(E[k]) : "f"(e0), "f"(e1));
    }

    // ---- sequence scores (unary + binary): role-0 warp only ----
    const size_t tbase = (size_t)b * TT;
    float sc = 0.f;
    if (role == 0) {
        for (int t = lane; t < TT; t += 32) {
            if (t < L) {
                int tg = tags[tbase + t];
                sc += inputs[(tbase + t) * NN + tg];
                if (t >= 1) {
                    int tp = tags[tbase + t - 1];
                    sc += trans[tp * NN + tg];
                }
            }
        }
#pragma unroll
        for (int o = 16; o; o >>= 1) sc += __shfl_xor_sync(0xffffffffu, sc, o);
    }

    // ---- init: q(0) = exp(x0 - M0), C = M0 (M0 = x[0][0], scalar load) ----
    const float* xp = inputs + tbase * NN;
    const float M0 = xp[0];
    float q = __expf(xp[j] - M0);
    pbuf[pair][0][j] = q;

    int Ce = 0;

    // x prefetch for owned column, depth 2
    float x1 = 0.f, x2 = 0.f;
    if (L > 1) x1 = xp[NN + j];
    if (L > 2) x2 = xp[2 * NN + j];

    asm volatile("bar.sync %0, 64;" :: "r"(barid) : "memory");

    for (int t = 1; t < L; ++t) {
        // ---- load full p vector (broadcast), 16 x 16B ----
        const unsigned s0 =
            (unsigned)__cvta_generic_to_shared(&pbuf[pair][(t - 1) & 1][0]);
        unsigned long long v[32];
#pragma unroll
        for (int k = 0; k < 16; ++k) {
            asm volatile("ld.shared.v2.u64 {%0,%1}, [%2];"
                         : "=l"(v[2 * k]), "=l"(v[2 * k + 1])
                         : "r"(s0 + 16 * k));
        }

        // off-chain: exp(x_t) and x prefetch (overlaps LDS latency)
        const float sx = __expf(x1);
        x1 = x2;
        if (t + 2 < L) x2 = xp[(size_t)(t + 2) * NN + j];

        // renorm scale from exponent of q_0 (low word of v[0])
        unsigned q0bits;
        asm("mov.b64 {%0,_}, %1;" : "=r"(q0bits) : "l"(v[0]));
        const int e = (int)((q0bits >> 23) & 0xff) - 127;
        Ce += e;
        const float scale = __uint_as_float((unsigned)(127 - e) << 23); // 2^-e
        const float s2 = sx * scale;

        // ---- 32 x fma.f32x2, 4 accumulator chains ----
        unsigned long long a0 = 0ull, a1 = 0ull, a2 = 0ull, a3 = 0ull;
#pragma unroll
        for (int k = 0; k < 32; k += 4) {
            asm("fma.rn.f32x2 %0, %1, %2, %0;" : "+l"(a0) : "l"(E[k])     , "l"(v[k]));
            asm("fma.rn.f32x2 %0, %1, %2, %0;" : "+l"(a1) : "l"(E[k + 1]) , "l"(v[k + 1]));
            asm("fma.rn.f32x2 %0, %1, %2, %0;" : "+l"(a2) : "l"(E[k + 2]) , "l"(v[k + 2]));
            asm("fma.rn.f32x2 %0, %1, %2, %0;" : "+l"(a3) : "l"(E[k + 3]) , "l"(v[k + 3]));
        }
        asm("add.rn.f32x2 %0, %0, %1;" : "+l"(a0) : "l"(a1));
        asm("add.rn.f32x2 %0, %0, %1;" : "+l"(a2) : "l"(a3));
        asm("add.rn.f32x2 %0, %0, %1;" : "+l"(a0) : "l"(a2));
        float gl, gh;
        asm("mov.b64 {%0,%1}, %2;" : "=f"(gl), "=f"(gh) : "l"(a0));

        q = (gl + gh) * s2;

        pbuf[pair][t & 1][j] = q;
        asm volatile("bar.sync %0, 64;" :: "r"(barid) : "memory");
    }

    // ---- log_norm = M0 + Ce*ln2 + log(sum_j q_j) ----
    float s = q;
#pragma unroll
    for (int o = 16; o; o >>= 1) s += __shfl_xor_sync(0xffffffffu, s, o);
    if (lane == 0) ssum[pair][role] = s;
    asm volatile("bar.sync %0, 64;" :: "r"(barid) : "memory");

    if (role == 0 && lane == 0) {
        const float stot = ssum[pair][0] + ssum[pair][1];
        const float log_norm =
            M0 + (float)Ce * 0.6931471805599453f + __logf(stot);
        out[b] = sc - log_norm;
    }
}

extern "C" void kernel_launch(void* const* d_in, const int* in_sizes, int n_in,
                              void* d_out, int out_size)
{
    const float* inputs = (const float*)d_in[0];
    const float* trans  = (const float*)d_in[1];
    const int*   tags   = (const int*)d_in[2];
    const int*   lens   = (const int*)d_in[3];
    float*       out    = (float*)d_out;

    crf_fwd_kernel<<<BB / 4, 256>>>(inputs, trans, tags, lens, out);
}

// round 5
// speedup vs baseline: 1.2162x; 1.2162x over previous
#include <cuda_runtime.h>
#include <cstdint>

#define BB 512
#define TT 1024
#define NN 64
#define WPB 4   // warps (= batches) per block

// One warp per batch (R3 mapping: 4 warps/block -> one per SMSP, 128 blocks
// -> <=1 warp per SMSP chip-wide). Thread `lane` owns columns lane, lane+32.
//
// Linear-domain recurrence with integer-exponent renormalization:
//   q_j(t+1) = exp(x_j(t+1)) * (sum_i q_i(t) * E_ij) * 2^{-e_t}
// E = exp(trans) register-resident, packed over ROW pairs. The p vector is
// read as 4 software-pipelined chunks of 4 x ld.shared.v2.u64 so the LDS
// latency hides inside the rt-3 issue gaps of the fma.f32x2 stream.
__global__ __launch_bounds__(32 * WPB, 1) void crf_fwd_kernel(
    const float* __restrict__ inputs,   // [B, T, N] fp32
    const float* __restrict__ trans,    // [N, N] fp32
    const int*   __restrict__ tags,     // [B, T] int32
    const int*   __restrict__ lens,     // [B] int32
    float*       __restrict__ out)      // [B] fp32
{
    const int lane = threadIdx.x & 31;
    const int wid  = threadIdx.x >> 5;
    const int b    = blockIdx.x * WPB + wid;
    const int L    = lens[b];

    __shared__ __align__(16) float pbuf[WPB][2][NN];

    // ---- E = exp(trans), packed over row pairs ----
    unsigned long long Ea[NN / 2], Eb[NN / 2];
#pragma unroll
    for (int k = 0; k < NN / 2; ++k) {
        float e0 = __expf(trans[(2 * k)     * NN + lane]);
        float e1 = __expf(trans[(2 * k + 1) * NN + lane]);
        asm("mov.b64 %0, {%1,%2};" : "=l"(Ea[k]) : "f"(e0), "f"(e1));
        float f0 = __expf(trans[(2 * k)     * NN + lane + 32]);
        float f1 = __expf(trans[(2 * k + 1) * NN + lane + 32]);
        asm("mov.b64 %0, {%1,%2};" : "=l"(Eb[k]) : "f"(f0), "f"(f1));
    }

    // ---- sequence scores (unary + binary), lanes strided over t ----
    const size_t tbase = (size_t)b * TT;
    float sc = 0.f;
    for (int t = lane; t < TT; t += 32) {
        if (t < L) {
            int tg = tags[tbase + t];
            sc += inputs[(tbase + t) * NN + tg];
            if (t >= 1) {
                int tp = tags[tbase + t - 1];
                sc += trans[tp * NN + tg];
            }
        }
    }
#pragma unroll
    for (int o = 16; o; o >>= 1) sc += __shfl_xor_sync(0xffffffffu, sc, o);

    // ---- init: q(0) = exp(x0 - M0), C = M0 ----
    const float* xp = inputs + tbase * NN;
    float x0a = xp[lane];
    float x0b = xp[lane + 32];
    float M0  = __shfl_sync(0xffffffffu, x0a, 0);
    float qa  = __expf(x0a - M0);
    float qb  = __expf(x0b - M0);
    pbuf[wid][0][lane]      = qa;
    pbuf[wid][0][lane + 32] = qb;
    __syncwarp();

    int Ce = 0;

    // x prefetch, depth 2
    float xa1 = 0.f, xb1 = 0.f, xa2 = 0.f, xb2 = 0.f;
    if (L > 1) { xa1 = xp[NN + lane];     xb1 = xp[NN + lane + 32]; }
    if (L > 2) { xa2 = xp[2 * NN + lane]; xb2 = xp[2 * NN + lane + 32]; }

#define LOAD_CHUNK(dst, base)                                                 \
    do {                                                                      \
        asm volatile("ld.shared.v2.u64 {%0,%1}, [%2];"                        \
                     : "=l"(dst[0]), "=l"(dst[1]) : "r"(base));               \
        asm volatile("ld.shared.v2.u64 {%0,%1}, [%2];"                        \
                     : "=l"(dst[2]), "=l"(dst[3]) : "r"((base) + 16));        \
        asm volatile("ld.shared.v2.u64 {%0,%1}, [%2];"                        \
                     : "=l"(dst[4]), "=l"(dst[5]) : "r"((base) + 32));        \
        asm volatile("ld.shared.v2.u64 {%0,%1}, [%2];"                        \
                     : "=l"(dst[6]), "=l"(dst[7]) : "r"((base) + 48));        \
    } while (0)

#define FMA_CHUNK(g, vv)                                                      \
    do {                                                                      \
        _Pragma("unroll")                                                     \
        for (int k = 0; k < 8; k += 4) {                                      \
            asm("fma.rn.f32x2 %0, %1, %2, %0;" : "+l"(a0) : "l"(Ea[8*(g)+k])    , "l"(vv[k]));     \
            asm("fma.rn.f32x2 %0, %1, %2, %0;" : "+l"(b0) : "l"(Eb[8*(g)+k])    , "l"(vv[k]));     \
            asm("fma.rn.f32x2 %0, %1, %2, %0;" : "+l"(a1) : "l"(Ea[8*(g)+k+1])  , "l"(vv[k+1]));   \
            asm("fma.rn.f32x2 %0, %1, %2, %0;" : "+l"(b1) : "l"(Eb[8*(g)+k+1])  , "l"(vv[k+1]));   \
            asm("fma.rn.f32x2 %0, %1, %2, %0;" : "+l"(a2) : "l"(Ea[8*(g)+k+2])  , "l"(vv[k+2]));   \
            asm("fma.rn.f32x2 %0, %1, %2, %0;" : "+l"(b2) : "l"(Eb[8*(g)+k+2])  , "l"(vv[k+2]));   \
            asm("fma.rn.f32x2 %0, %1, %2, %0;" : "+l"(a3) : "l"(Ea[8*(g)+k+3])  , "l"(vv[k+3]));   \
            asm("fma.rn.f32x2 %0, %1, %2, %0;" : "+l"(b3) : "l"(Eb[8*(g)+k+3])  , "l"(vv[k+3]));   \
        }                                                                     \
    } while (0)

    for (int t = 1; t < L; ++t) {
        const unsigned s0 =
            (unsigned)__cvta_generic_to_shared(&pbuf[wid][(t - 1) & 1][0]);
        unsigned long long v0[8], v1[8];

        LOAD_CHUNK(v0, s0);          // rows  0..15

        // off-chain: exp(x_t) and x prefetch (fills LDS shadow)
        const float sxa = __expf(xa1);
        const float sxb = __expf(xb1);
        xa1 = xa2; xb1 = xb2;
        if (t + 2 < L) {
            xa2 = xp[(size_t)(t + 2) * NN + lane];
            xb2 = xp[(size_t)(t + 2) * NN + lane + 32];
        }

        LOAD_CHUNK(v1, s0 + 64);     // rows 16..31

        // renorm scale from exponent of q_0 (low word of v0[0])
        unsigned q0bits;
        asm("mov.b64 {%0,_}, %1;" : "=r"(q0bits) : "l"(v0[0]));
        const int e = (int)((q0bits >> 23) & 0xff) - 127;
        Ce += e;
        const float scale = __uint_as_float((unsigned)(127 - e) << 23); // 2^-e
        const float s2a = sxa * scale;
        const float s2b = sxb * scale;

        unsigned long long a0 = 0ull, a1 = 0ull, a2 = 0ull, a3 = 0ull;
        unsigned long long b0 = 0ull, b1 = 0ull, b2 = 0ull, b3 = 0ull;

        FMA_CHUNK(0, v0);
        LOAD_CHUNK(v0, s0 + 128);    // rows 32..47
        FMA_CHUNK(1, v1);
        LOAD_CHUNK(v1, s0 + 192);    // rows 48..63
        FMA_CHUNK(2, v0);
        FMA_CHUNK(3, v1);

        asm("add.rn.f32x2 %0, %0, %1;" : "+l"(a0) : "l"(a1));
        asm("add.rn.f32x2 %0, %0, %1;" : "+l"(a2) : "l"(a3));
        asm("add.rn.f32x2 %0, %0, %1;" : "+l"(b0) : "l"(b1));
        asm("add.rn.f32x2 %0, %0, %1;" : "+l"(b2) : "l"(b3));
        asm("add.rn.f32x2 %0, %0, %1;" : "+l"(a0) : "l"(a2));
        asm("add.rn.f32x2 %0, %0, %1;" : "+l"(b0) : "l"(b2));
        float gal, gah, gbl, gbh;
        asm("mov.b64 {%0,%1}, %2;" : "=f"(gal), "=f"(gah) : "l"(a0));
        asm("mov.b64 {%0,%1}, %2;" : "=f"(gbl), "=f"(gbh) : "l"(b0));

        qa = (gal + gah) * s2a;
        qb = (gbl + gbh) * s2b;

        float* pw = pbuf[wid][t & 1];
        pw[lane]      = qa;
        pw[lane + 32] = qb;
        __syncwarp();
    }

    // ---- log_norm = M0 + Ce*ln2 + log(sum_j q_j) ----
    float s = qa + qb;
#pragma unroll
    for (int o = 16; o; o >>= 1) s += __shfl_xor_sync(0xffffffffu, s, o);

    if (lane == 0) {
        const float log_norm = M0 + (float)Ce * 0.6931471805599453f + __logf(s);
        out[b] = sc - log_norm;
    }
}

extern "C" void kernel_launch(void* const* d_in, const int* in_sizes, int n_in,
                              void* d_out, int out_size)
{
    const float* inputs = (const float*)d_in[0];
    const float* trans  = (const float*)d_in[1];
    const int*   tags   = (const int*)d_in[2];
    const int*   lens   = (const int*)d_in[3];
    float*       out    = (float*)d_out;

    crf_fwd_kernel<<<BB / WPB, 32 * WPB>>>(inputs, trans, tags, lens, out);
}